// round 3
// baseline (speedup 1.0000x reference)
#include <cuda_runtime.h>
#include <cuda_bf16.h>
#include <math.h>

#define N_RES 384
#define C_S   384
#define C_Z   128
#define N_HEAD 12
#define CDIM  16
#define N_QP  4
#define N_PV  8

// ---------------- scratch (device globals; no allocation) ----------------
__device__ __align__(16) float g_q  [N_RES * N_HEAD * CDIM];   // [i][h*16+c]
__device__ __align__(16) float g_k  [N_RES * N_HEAD * CDIM];
__device__ __align__(16) float g_v  [N_RES * N_HEAD * CDIM];
__device__ __align__(16) float g_qpl[N_RES * 3 * N_HEAD * N_QP]; // [i][d*48+h*4+p]
__device__ __align__(16) float g_kpl[N_RES * 3 * N_HEAD * N_QP];
__device__ __align__(16) float g_vpl[N_RES * 3 * N_HEAD * N_PV]; // [i][d*96+h*8+k]
__device__ __align__(16) float g_tq [N_HEAD * N_QP * 3 * N_RES]; // [(h*4+p)*3+d][i]
__device__ __align__(16) float g_tk [N_HEAD * N_QP * 3 * N_RES];
__device__ __align__(16) float g_vcat[N_HEAD * N_RES * 40];      // [h][j][0:16 v, 16+k*3+d vt]
__device__ __align__(16) float g_bias[N_HEAD * N_RES * N_RES];   // [h][i][j]
__device__ __align__(16) float g_att [N_HEAD * N_RES * N_RES];   // [h][i][j]
__device__ __align__(16) float g_eo  [N_HEAD * N_RES * 40];      // [h][i][40]
__device__ __align__(16) float g_cat [N_RES * 2112];             // concat per residue

// ---------------- generic tiled SGEMM: C = A(MxK) @ B(KxN) + bias ----------------
__global__ void sgemm_bias(const float* __restrict__ A, const float* __restrict__ B,
                           const float* __restrict__ bias, float* __restrict__ Cm,
                           int M, int K, int N) {
    __shared__ float As[32][33];
    __shared__ float Bs[32][33];
    int tx = threadIdx.x, ty = threadIdx.y;         // 16x16
    int row0 = blockIdx.y * 32, col0 = blockIdx.x * 32;
    float a00 = 0.f, a01 = 0.f, a10 = 0.f, a11 = 0.f;
    for (int k0 = 0; k0 < K; k0 += 32) {
        #pragma unroll
        for (int l = 0; l < 4; l++) {
            int r = ty + (l / 2) * 16, c = tx + (l % 2) * 16;
            int gr = row0 + r, gc = k0 + c;
            As[r][c] = (gr < M && gc < K) ? A[(size_t)gr * K + gc] : 0.f;
            gr = k0 + r; gc = col0 + c;
            Bs[r][c] = (gr < K && gc < N) ? B[(size_t)gr * N + gc] : 0.f;
        }
        __syncthreads();
        #pragma unroll
        for (int kk = 0; kk < 32; kk++) {
            float x0 = As[ty][kk], x1 = As[ty + 16][kk];
            float y0 = Bs[kk][tx], y1 = Bs[kk][tx + 16];
            a00 += x0 * y0; a01 += x0 * y1; a10 += x1 * y0; a11 += x1 * y1;
        }
        __syncthreads();
    }
    int r0 = row0 + ty, r1 = row0 + ty + 16, c0 = col0 + tx, c1 = col0 + tx + 16;
    if (r0 < M) {
        if (c0 < N) Cm[(size_t)r0 * N + c0] = a00 + bias[c0];
        if (c1 < N) Cm[(size_t)r0 * N + c1] = a01 + bias[c1];
    }
    if (r1 < M) {
        if (c0 < N) Cm[(size_t)r1 * N + c0] = a10 + bias[c0];
        if (c1 < N) Cm[(size_t)r1 * N + c1] = a11 + bias[c1];
    }
}

// ---------------- bias = moveaxis(z @ Wb + bb): [h][i][j] ----------------
__global__ void bias_kernel(const float* __restrict__ z, const float* __restrict__ Wb,
                            const float* __restrict__ bb) {
    __shared__ float wbs[C_Z * N_HEAD];
    __shared__ float bbs[N_HEAD];
    int tid = threadIdx.x;   // 256
    for (int i = tid; i < C_Z * N_HEAD; i += 256) wbs[i] = Wb[i];
    if (tid < N_HEAD) bbs[tid] = bb[tid];
    __syncthreads();
    int warp = tid >> 5, lane = tid & 31;
    int row = blockIdx.x * 8 + warp;                 // flattened (i,j)
    if (row >= N_RES * N_RES) return;
    float4 z4 = ((const float4*)(z + (size_t)row * C_Z))[lane];  // c = lane*4..lane*4+3
    float part[N_HEAD];
    int cb = lane * 4;
    #pragma unroll
    for (int h = 0; h < N_HEAD; h++) {
        part[h] = z4.x * wbs[(cb + 0) * N_HEAD + h] + z4.y * wbs[(cb + 1) * N_HEAD + h]
                + z4.z * wbs[(cb + 2) * N_HEAD + h] + z4.w * wbs[(cb + 3) * N_HEAD + h];
    }
    #pragma unroll
    for (int off = 16; off > 0; off >>= 1)
        #pragma unroll
        for (int h = 0; h < N_HEAD; h++)
            part[h] += __shfl_down_sync(0xffffffffu, part[h], off);
    if (lane == 0) {
        #pragma unroll
        for (int h = 0; h < N_HEAD; h++)
            g_bias[(size_t)h * (N_RES * N_RES) + row] = part[h] + bbs[h];
    }
}

// ---------------- transform points with frames; build tq/tk SoA + vcat ----------------
__global__ void transform_kernel(const float* __restrict__ T) {
    int i = blockIdx.x;
    int tid = threadIdx.x;   // 128
    __shared__ float Rm[9], tv[3];
    if (tid < 9) Rm[tid] = T[i * 16 + (tid / 3) * 4 + (tid % 3)];
    if (tid < 3) tv[tid] = T[i * 16 + tid * 4 + 3];
    __syncthreads();
    // q / k points: 48 each
    if (tid < 96) {
        int set = tid / 48, hp = tid % 48;
        const float* src = set ? g_kpl : g_qpl;
        float lx = src[i * 144 + 0 * 48 + hp];
        float ly = src[i * 144 + 1 * 48 + hp];
        float lz = src[i * 144 + 2 * 48 + hp];
        float gx = Rm[0] * lx + Rm[1] * ly + Rm[2] * lz + tv[0];
        float gy = Rm[3] * lx + Rm[4] * ly + Rm[5] * lz + tv[1];
        float gz = Rm[6] * lx + Rm[7] * ly + Rm[8] * lz + tv[2];
        float* dst = set ? g_tk : g_tq;
        dst[(hp * 3 + 0) * N_RES + i] = gx;
        dst[(hp * 3 + 1) * N_RES + i] = gy;
        dst[(hp * 3 + 2) * N_RES + i] = gz;
    }
    // v points: 96
    if (tid < 96) {
        int hp = tid;                 // h*8 + k
        float lx = g_vpl[i * 288 + 0 * 96 + hp];
        float ly = g_vpl[i * 288 + 1 * 96 + hp];
        float lz = g_vpl[i * 288 + 2 * 96 + hp];
        float gx = Rm[0] * lx + Rm[1] * ly + Rm[2] * lz + tv[0];
        float gy = Rm[3] * lx + Rm[4] * ly + Rm[5] * lz + tv[1];
        float gz = Rm[6] * lx + Rm[7] * ly + Rm[8] * lz + tv[2];
        int h = hp / 8, k = hp % 8;
        float* d = &g_vcat[((size_t)h * N_RES + i) * 40 + 16 + k * 3];
        d[0] = gx; d[1] = gy; d[2] = gz;
    }
    // copy v into vcat cols 0..15
    for (int c = tid; c < N_HEAD * CDIM; c += 128) {
        int h = c / CDIM, cc = c % CDIM;
        g_vcat[((size_t)h * N_RES + i) * 40 + cc] = g_v[i * (N_HEAD * CDIM) + c];
    }
}

// ---------------- attention logits + softmax per (h,i) ----------------
__global__ void attn_kernel(const float* __restrict__ hw) {
    const float WL  = 0.5773502691896258f;   // sqrt(1/3)
    const float WC2 = 0.11785113019775793f;  // sqrt(2/(9*4))/2
    int hi = blockIdx.x;
    int h = hi / N_RES, i = hi % N_RES;
    int tid = threadIdx.x;   // 128
    __shared__ float qs[CDIM];
    __shared__ float tqs[N_QP * 3];
    __shared__ float red[128];
    __shared__ float logits[N_RES];
    if (tid < CDIM) qs[tid] = g_q[i * (N_HEAD * CDIM) + h * CDIM + tid] * 0.25f; // 1/sqrt(C)
    if (tid < 12) {
        int p = tid / 3, d = tid % 3;
        tqs[tid] = g_tq[((h * N_QP + p) * 3 + d) * N_RES + i];
    }
    __syncthreads();
    float gam = log1pf(__expf(hw[h]));
    float coef = gam * WC2;
    const float* brow = &g_bias[((size_t)h * N_RES + i) * N_RES];
    float lmax = -1e30f;
    #pragma unroll
    for (int t = 0; t < 3; t++) {
        int j = tid + t * 128;
        const float* kp = &g_k[j * (N_HEAD * CDIM) + h * CDIM];
        float qk = 0.f;
        #pragma unroll
        for (int c = 0; c < CDIM; c++) qk += qs[c] * kp[c];
        float dist = 0.f;
        #pragma unroll
        for (int p = 0; p < N_QP; p++) {
            float dx = tqs[p * 3 + 0] - g_tk[((h * N_QP + p) * 3 + 0) * N_RES + j];
            float dy = tqs[p * 3 + 1] - g_tk[((h * N_QP + p) * 3 + 1) * N_RES + j];
            float dz = tqs[p * 3 + 2] - g_tk[((h * N_QP + p) * 3 + 2) * N_RES + j];
            dist += dx * dx + dy * dy + dz * dz;
        }
        float lg = WL * (qk + brow[j] - coef * dist);
        logits[j] = lg;
        lmax = fmaxf(lmax, lg);
    }
    red[tid] = lmax; __syncthreads();
    for (int s = 64; s > 0; s >>= 1) { if (tid < s) red[tid] = fmaxf(red[tid], red[tid + s]); __syncthreads(); }
    float m = red[0]; __syncthreads();
    float lsum = 0.f;
    #pragma unroll
    for (int t = 0; t < 3; t++) {
        int j = tid + t * 128;
        float e = __expf(logits[j] - m);
        logits[j] = e;
        lsum += e;
    }
    red[tid] = lsum; __syncthreads();
    for (int s = 64; s > 0; s >>= 1) { if (tid < s) red[tid] += red[tid + s]; __syncthreads(); }
    float inv = 1.f / red[0];
    float* arow = &g_att[((size_t)h * N_RES + i) * N_RES];
    #pragma unroll
    for (int t = 0; t < 3; t++) {
        int j = tid + t * 128;
        arow[j] = logits[j] * inv;
    }
}

// ---------------- pairwise = einsum(z[i,j,c], att[h,i,j]) -> cat[i][576 + h*128 + c] ----------------
__global__ void pairwise_kernel(const float* __restrict__ z) {
    int i = blockIdx.x;
    int tid = threadIdx.x;   // 128
    __shared__ float att_s[N_HEAD][N_RES];
    __shared__ float4 part4[4][N_HEAD][32];
    for (int idx = tid; idx < N_HEAD * N_RES; idx += 128) {
        int h = idx / N_RES, j = idx % N_RES;
        att_s[h][j] = g_att[((size_t)h * N_RES + i) * N_RES + j];
    }
    __syncthreads();
    int c4 = tid & 31, jr = tid >> 5;
    const float4* zp = (const float4*)(z + (size_t)i * N_RES * C_Z);
    float4 acc[N_HEAD];
    #pragma unroll
    for (int h = 0; h < N_HEAD; h++) acc[h] = make_float4(0.f, 0.f, 0.f, 0.f);
    for (int j = jr; j < N_RES; j += 4) {
        float4 zv = zp[j * 32 + c4];
        #pragma unroll
        for (int h = 0; h < N_HEAD; h++) {
            float a = att_s[h][j];
            acc[h].x += a * zv.x; acc[h].y += a * zv.y;
            acc[h].z += a * zv.z; acc[h].w += a * zv.w;
        }
    }
    #pragma unroll
    for (int h = 0; h < N_HEAD; h++) part4[jr][h][c4] = acc[h];
    __syncthreads();
    if (jr == 0) {
        #pragma unroll
        for (int h = 0; h < N_HEAD; h++) {
            float4 s0 = part4[0][h][c4], s1 = part4[1][h][c4];
            float4 s2 = part4[2][h][c4], s3 = part4[3][h][c4];
            float4 r = make_float4(s0.x + s1.x + s2.x + s3.x, s0.y + s1.y + s2.y + s3.y,
                                   s0.z + s1.z + s2.z + s3.z, s0.w + s1.w + s2.w + s3.w);
            *((float4*)&g_cat[(size_t)i * 2112 + 576 + h * C_Z + c4 * 4]) = r;
        }
    }
}

// ---------------- eo[h][i][40] = att[h] @ vcat[h] ----------------
__global__ void vatt_kernel() {
    int h = blockIdx.y;
    int i0 = blockIdx.x * 32;
    __shared__ float at[32][33];
    __shared__ float vc[32][41];
    int tid = threadIdx.x;   // 320
    int col = tid % 40, rgrp = tid / 40;   // rgrp 0..7
    float acc[4] = {0.f, 0.f, 0.f, 0.f};
    for (int j0 = 0; j0 < N_RES; j0 += 32) {
        for (int idx = tid; idx < 1024; idx += 320) {
            int r = idx / 32, c = idx % 32;
            at[r][c] = g_att[((size_t)h * N_RES + i0 + r) * N_RES + j0 + c];
        }
        for (int idx = tid; idx < 1280; idx += 320) {
            int r = idx / 40, c = idx % 40;
            vc[r][c] = g_vcat[((size_t)h * N_RES + j0 + r) * 40 + c];
        }
        __syncthreads();
        #pragma unroll 8
        for (int jj = 0; jj < 32; jj++) {
            float b = vc[jj][col];
            #pragma unroll
            for (int rr = 0; rr < 4; rr++) acc[rr] += at[rgrp + rr * 8][jj] * b;
        }
        __syncthreads();
    }
    #pragma unroll
    for (int rr = 0; rr < 4; rr++)
        g_eo[((size_t)h * N_RES + i0 + rgrp + rr * 8) * 40 + col] = acc[rr];
}

// ---------------- inverse warp, norms, assemble cat cols [0,576) ----------------
__global__ void post_kernel(const float* __restrict__ T) {
    int t = blockIdx.x * blockDim.x + threadIdx.x;
    if (t >= N_HEAD * N_RES) return;
    int h = t / N_RES, i = t % N_RES;
    const float* e = &g_eo[(size_t)t * 40];    // NOTE: t = h*N_RES+i matches eo layout
    float* catp = &g_cat[(size_t)i * 2112];
    #pragma unroll
    for (int c = 0; c < CDIM; c++) catp[h * CDIM + c] = e[c];
    float R[9], tv[3];
    #pragma unroll
    for (int d = 0; d < 9; d++) R[d] = T[i * 16 + (d / 3) * 4 + (d % 3)];
    #pragma unroll
    for (int d = 0; d < 3; d++) tv[d] = T[i * 16 + d * 4 + 3];
    #pragma unroll
    for (int k = 0; k < N_PV; k++) {
        float px = e[16 + k * 3 + 0] - tv[0];
        float py = e[16 + k * 3 + 1] - tv[1];
        float pz = e[16 + k * 3 + 2] - tv[2];
        float lx = R[0] * px + R[3] * py + R[6] * pz;
        float ly = R[1] * px + R[4] * py + R[7] * pz;
        float lz = R[2] * px + R[5] * py + R[8] * pz;
        catp[192 + 0 * 96 + h * N_PV + k] = lx;
        catp[192 + 1 * 96 + h * N_PV + k] = ly;
        catp[192 + 2 * 96 + h * N_PV + k] = lz;
        catp[480 + h * N_PV + k] = sqrtf(lx * lx + ly * ly + lz * lz);
    }
}

extern "C" void kernel_launch(void* const* d_in, const int* in_sizes, int n_in,
                              void* d_out, int out_size) {
    const float* s   = (const float*)d_in[0];
    const float* z   = (const float*)d_in[1];
    const float* T   = (const float*)d_in[2];
    const float* Wq  = (const float*)d_in[3];
    const float* bq  = (const float*)d_in[4];
    const float* Wk  = (const float*)d_in[5];
    const float* bk  = (const float*)d_in[6];
    const float* Wv  = (const float*)d_in[7];
    const float* bv  = (const float*)d_in[8];
    const float* Wqp = (const float*)d_in[9];
    const float* bqp = (const float*)d_in[10];
    const float* Wkp = (const float*)d_in[11];
    const float* bkp = (const float*)d_in[12];
    const float* Wvp = (const float*)d_in[13];
    const float* bvp = (const float*)d_in[14];
    const float* Wb  = (const float*)d_in[15];
    const float* bb  = (const float*)d_in[16];
    const float* Wo  = (const float*)d_in[17];
    const float* bo  = (const float*)d_in[18];
    const float* hw  = (const float*)d_in[19];
    float* out = (float*)d_out;

    float *p_q, *p_k, *p_v, *p_qpl, *p_kpl, *p_vpl, *p_cat;
    cudaGetSymbolAddress((void**)&p_q,   g_q);
    cudaGetSymbolAddress((void**)&p_k,   g_k);
    cudaGetSymbolAddress((void**)&p_v,   g_v);
    cudaGetSymbolAddress((void**)&p_qpl, g_qpl);
    cudaGetSymbolAddress((void**)&p_kpl, g_kpl);
    cudaGetSymbolAddress((void**)&p_vpl, g_vpl);
    cudaGetSymbolAddress((void**)&p_cat, g_cat);

    dim3 thr(16, 16);
    // projections
    sgemm_bias<<<dim3(6, 12),  thr>>>(s, Wq,  bq,  p_q,   N_RES, C_S, 192);
    sgemm_bias<<<dim3(6, 12),  thr>>>(s, Wk,  bk,  p_k,   N_RES, C_S, 192);
    sgemm_bias<<<dim3(6, 12),  thr>>>(s, Wv,  bv,  p_v,   N_RES, C_S, 192);
    sgemm_bias<<<dim3(5, 12),  thr>>>(s, Wqp, bqp, p_qpl, N_RES, C_S, 144);
    sgemm_bias<<<dim3(5, 12),  thr>>>(s, Wkp, bkp, p_kpl, N_RES, C_S, 144);
    sgemm_bias<<<dim3(9, 12),  thr>>>(s, Wvp, bvp, p_vpl, N_RES, C_S, 288);
    // bias from z
    bias_kernel<<<(N_RES * N_RES) / 8, 256>>>(z, Wb, bb);
    // frame transforms
    transform_kernel<<<N_RES, 128>>>(T);
    // attention
    attn_kernel<<<N_HEAD * N_RES, 128>>>(hw);
    // pairwise (writes cat[576:2112))
    pairwise_kernel<<<N_RES, 128>>>(z);
    // att @ [v|vt]
    vatt_kernel<<<dim3(12, 12), 320>>>();
    // inverse warp + norms + concat (writes cat[0:576))
    post_kernel<<<36, 128>>>(T);
    // final projection
    sgemm_bias<<<dim3(12, 12), thr>>>(p_cat, Wo, bo, out, N_RES, 2112, C_S);
}

// round 6
// speedup vs baseline: 2.2838x; 2.2838x over previous
#include <cuda_runtime.h>
#include <cuda_bf16.h>
#include <math.h>

#define N_RES 384
#define C_S   384
#define C_Z   128
#define N_HEAD 12
#define CDIM  16
#define N_QP  4
#define N_PV  8
#define NP    1152   // total projection output cols: 192*3 + 144*2 + 288

// ---------------- scratch (device globals; no allocation) ----------------
__device__ __align__(16) float g_proj[N_RES * NP];               // [i][1152]
__device__ __align__(16) float g_Wcat[C_S * NP];                 // concat weights
__device__ __align__(16) float g_bcat[NP];                       // concat biases
__device__ __align__(16) float g_tq [N_HEAD * N_QP * 3 * N_RES]; // [(h*4+p)*3+d][i]
__device__ __align__(16) float g_tk [N_HEAD * N_QP * 3 * N_RES];
__device__ __align__(16) float g_vcat[N_HEAD * N_RES * 40];      // [h][j][0:16 v, 16+k*3+d vt]
__device__ __align__(16) float g_bias[N_HEAD * N_RES * N_RES];   // [h][i][j]
__device__ __align__(16) float g_att [N_HEAD * N_RES * N_RES];   // [h][i][j]
__device__ __align__(16) float g_eo  [N_HEAD * N_RES * 40];      // [h][i][40]
__device__ __align__(16) float g_cat [N_RES * 2112];             // concat per residue
__device__ __align__(16) float g_part[4 * N_RES * C_S];          // split-K partials

// ---------------- prep: concat weights/biases into g_Wcat/g_bcat ----------------
__global__ void prep_w(const float* __restrict__ Wq, const float* __restrict__ Wk,
                       const float* __restrict__ Wv, const float* __restrict__ Wqp,
                       const float* __restrict__ Wkp, const float* __restrict__ Wvp,
                       const float* __restrict__ bq, const float* __restrict__ bk,
                       const float* __restrict__ bv, const float* __restrict__ bqp,
                       const float* __restrict__ bkp, const float* __restrict__ bvp) {
    int idx = blockIdx.x * blockDim.x + threadIdx.x;
    if (idx < C_S * NP) {
        int r = idx / NP, c = idx % NP;
        float w;
        if      (c < 192) w = Wq [r * 192 + c];
        else if (c < 384) w = Wk [r * 192 + c - 192];
        else if (c < 576) w = Wv [r * 192 + c - 384];
        else if (c < 720) w = Wqp[r * 144 + c - 576];
        else if (c < 864) w = Wkp[r * 144 + c - 720];
        else              w = Wvp[r * 288 + c - 864];
        g_Wcat[idx] = w;
    } else if (idx < C_S * NP + NP) {
        int c = idx - C_S * NP;
        float b;
        if      (c < 192) b = bq [c];
        else if (c < 384) b = bk [c - 192];
        else if (c < 576) b = bv [c - 384];
        else if (c < 720) b = bqp[c - 576];
        else if (c < 864) b = bkp[c - 720];
        else              b = bvp[c - 864];
        g_bcat[c] = b;
    }
}

// ---------------- 64x64 tile / 4x4 microtile SGEMM (M fixed = 384) ----------------
// C[z] = A[:, kb:kb+kPerSplit] @ B[kb:kb+kPerSplit, :]  (+ bias if non-null)
__global__ void gemm64(const float* __restrict__ A, int lda,
                       const float* __restrict__ B, int ldb,
                       const float* __restrict__ bias,
                       float* __restrict__ C, int ldc,
                       int kPerSplit) {
    __shared__ float As[16][64];   // transposed: As[k][m]
    __shared__ float Bs[16][64];
    int tid = threadIdx.x;
    int tx = tid & 15, ty = tid >> 4;
    int row0 = blockIdx.y * 64, col0 = blockIdx.x * 64;
    int kb = blockIdx.z * kPerSplit;
    C += (size_t)blockIdx.z * N_RES * ldc;
    float acc[4][4] = {};
    int am = tid >> 2, ak = (tid & 3) * 4;
    int bk = tid >> 4, bn = (tid & 15) * 4;
    for (int kt = kb; kt < kb + kPerSplit; kt += 16) {
        float4 a4 = *(const float4*)&A[(size_t)(row0 + am) * lda + kt + ak];
        float4 b4 = *(const float4*)&B[(size_t)(kt + bk) * ldb + col0 + bn];
        As[ak + 0][am] = a4.x; As[ak + 1][am] = a4.y;
        As[ak + 2][am] = a4.z; As[ak + 3][am] = a4.w;
        *(float4*)&Bs[bk][bn] = b4;
        __syncthreads();
        #pragma unroll
        for (int kk = 0; kk < 16; kk++) {
            float4 av = *(const float4*)&As[kk][ty * 4];
            float4 bv = *(const float4*)&Bs[kk][tx * 4];
            acc[0][0] += av.x * bv.x; acc[0][1] += av.x * bv.y; acc[0][2] += av.x * bv.z; acc[0][3] += av.x * bv.w;
            acc[1][0] += av.y * bv.x; acc[1][1] += av.y * bv.y; acc[1][2] += av.y * bv.z; acc[1][3] += av.y * bv.w;
            acc[2][0] += av.z * bv.x; acc[2][1] += av.z * bv.y; acc[2][2] += av.z * bv.z; acc[2][3] += av.z * bv.w;
            acc[3][0] += av.w * bv.x; acc[3][1] += av.w * bv.y; acc[3][2] += av.w * bv.z; acc[3][3] += av.w * bv.w;
        }
        __syncthreads();
    }
    #pragma unroll
    for (int r = 0; r < 4; r++) {
        int gr = row0 + ty * 4 + r;
        float4 o = make_float4(acc[r][0], acc[r][1], acc[r][2], acc[r][3]);
        if (bias != nullptr) {
            const float* bp = &bias[col0 + tx * 4];
            o.x += bp[0]; o.y += bp[1]; o.z += bp[2]; o.w += bp[3];
        }
        *(float4*)&C[(size_t)gr * ldc + col0 + tx * 4] = o;
    }
}

// ---------------- reduce split-K partials + bias -> out ----------------
__global__ void reduce_out(const float* __restrict__ bo, float* __restrict__ out) {
    int idx = blockIdx.x * blockDim.x + threadIdx.x;  // over 36864 float4
    if (idx >= N_RES * C_S / 4) return;
    const float4* p = (const float4*)g_part;
    float4 a = p[idx], b = p[idx + 36864], c = p[idx + 2 * 36864], d = p[idx + 3 * 36864];
    int col = (idx * 4) % C_S;
    float4 r = make_float4(a.x + b.x + c.x + d.x + bo[col],
                           a.y + b.y + c.y + d.y + bo[col + 1],
                           a.z + b.z + c.z + d.z + bo[col + 2],
                           a.w + b.w + c.w + d.w + bo[col + 3]);
    ((float4*)out)[idx] = r;
}

// ---------------- bias = moveaxis(z @ Wb + bb): [h][i][j] ----------------
__global__ void bias_kernel(const float* __restrict__ z, const float* __restrict__ Wb,
                            const float* __restrict__ bb) {
    __shared__ float wbs[C_Z * N_HEAD];
    __shared__ float bbs[N_HEAD];
    int tid = threadIdx.x;   // 256
    for (int i = tid; i < C_Z * N_HEAD; i += 256) wbs[i] = Wb[i];
    if (tid < N_HEAD) bbs[tid] = bb[tid];
    __syncthreads();
    int warp = tid >> 5, lane = tid & 31;
    int row = blockIdx.x * 8 + warp;                 // flattened (i,j)
    if (row >= N_RES * N_RES) return;
    float4 z4 = ((const float4*)(z + (size_t)row * C_Z))[lane];
    float part[N_HEAD];
    int cb = lane * 4;
    #pragma unroll
    for (int h = 0; h < N_HEAD; h++) {
        part[h] = z4.x * wbs[(cb + 0) * N_HEAD + h] + z4.y * wbs[(cb + 1) * N_HEAD + h]
                + z4.z * wbs[(cb + 2) * N_HEAD + h] + z4.w * wbs[(cb + 3) * N_HEAD + h];
    }
    #pragma unroll
    for (int off = 16; off > 0; off >>= 1) {
        #pragma unroll
        for (int h = 0; h < N_HEAD; h++)
            part[h] += __shfl_down_sync(0xffffffffu, part[h], off);
    }
    if (lane == 0) {
        #pragma unroll
        for (int h = 0; h < N_HEAD; h++)
            g_bias[(size_t)h * (N_RES * N_RES) + row] = part[h] + bbs[h];
    }
}

// ---------------- transform points with frames; build tq/tk SoA + vcat ----------------
__global__ void transform_kernel(const float* __restrict__ T) {
    int i = blockIdx.x;
    int tid = threadIdx.x;   // 128
    __shared__ float Rm[9], tv[3];
    if (tid < 9) Rm[tid] = T[i * 16 + (tid / 3) * 4 + (tid % 3)];
    if (tid < 3) tv[tid] = T[i * 16 + tid * 4 + 3];
    __syncthreads();
    const float* prow = &g_proj[(size_t)i * NP];
    // q / k points: 48 each
    if (tid < 96) {
        int set = tid / 48, hp = tid % 48;
        int base = set ? 720 : 576;
        float lx = prow[base + 0 * 48 + hp];
        float ly = prow[base + 1 * 48 + hp];
        float lz = prow[base + 2 * 48 + hp];
        float gx = Rm[0] * lx + Rm[1] * ly + Rm[2] * lz + tv[0];
        float gy = Rm[3] * lx + Rm[4] * ly + Rm[5] * lz + tv[1];
        float gz = Rm[6] * lx + Rm[7] * ly + Rm[8] * lz + tv[2];
        float* dst = set ? g_tk : g_tq;
        dst[(hp * 3 + 0) * N_RES + i] = gx;
        dst[(hp * 3 + 1) * N_RES + i] = gy;
        dst[(hp * 3 + 2) * N_RES + i] = gz;
    }
    // v points: 96
    if (tid < 96) {
        int hp = tid;                 // h*8 + k
        float lx = prow[864 + 0 * 96 + hp];
        float ly = prow[864 + 1 * 96 + hp];
        float lz = prow[864 + 2 * 96 + hp];
        float gx = Rm[0] * lx + Rm[1] * ly + Rm[2] * lz + tv[0];
        float gy = Rm[3] * lx + Rm[4] * ly + Rm[5] * lz + tv[1];
        float gz = Rm[6] * lx + Rm[7] * ly + Rm[8] * lz + tv[2];
        int h = hp / 8, k = hp % 8;
        float* d = &g_vcat[((size_t)h * N_RES + i) * 40 + 16 + k * 3];
        d[0] = gx; d[1] = gy; d[2] = gz;
    }
    // copy v into vcat cols 0..15
    for (int c = tid; c < N_HEAD * CDIM; c += 128) {
        int h = c / CDIM, cc = c % CDIM;
        g_vcat[((size_t)h * N_RES + i) * 40 + cc] = prow[384 + c];
    }
}

// ---------------- tiled attention: block per (h, 32-row i-tile) ----------------
__global__ void attn_fused(const float* __restrict__ hw) {
    const float WL  = 0.5773502691896258f;   // sqrt(1/3)
    const float WC2 = 0.11785113019775793f;  // sqrt(2/(9*4))/2
    int h = blockIdx.y;
    int i0 = blockIdx.x * 32;
    int tid = threadIdx.x;   // 256
    __shared__ float ks [CDIM][N_RES];       // 24 KB
    __shared__ float tks[12][N_RES];         // 18 KB
    __shared__ float qs [32][CDIM];          // 2 KB
    __shared__ float tqs[32][12];            // 1.5 KB
    // load k for this head, transposed (SoA over j)
    for (int t = tid; t < N_RES * 4; t += 256) {   // 1536 float4 loads
        int j = t >> 2, cq = (t & 3) * 4;
        float4 kv = *(const float4*)&g_proj[(size_t)j * NP + 192 + h * CDIM + cq];
        ks[cq + 0][j] = kv.x; ks[cq + 1][j] = kv.y;
        ks[cq + 2][j] = kv.z; ks[cq + 3][j] = kv.w;
    }
    for (int t = tid; t < 12 * N_RES; t += 256) tks[t / N_RES][t % N_RES] = g_tk[h * 12 * N_RES + t];
    for (int t = tid; t < 32 * CDIM; t += 256) {
        int il = t / CDIM, c = t % CDIM;
        qs[il][c] = g_proj[(size_t)(i0 + il) * NP + h * CDIM + c] * 0.25f;  // 1/sqrt(C)
    }
    for (int t = tid; t < 32 * 12; t += 256) {
        int il = t / 12, pd = t % 12;
        tqs[il][pd] = g_tq[(h * 12 + pd) * N_RES + i0 + il];
    }
    __syncthreads();
    float gam = log1pf(__expf(hw[h]));
    float coef = gam * WC2;
    int w = tid >> 5, lane = tid & 31;
    #pragma unroll
    for (int rr = 0; rr < 4; rr++) {
        int il = w * 4 + rr;
        int i = i0 + il;
        const float* brow = &g_bias[((size_t)h * N_RES + i) * N_RES];
        float lreg[12];
        float lmax = -1e30f;
        #pragma unroll
        for (int jj = 0; jj < 12; jj++) {
            int j = lane + jj * 32;
            float qk = 0.f;
            #pragma unroll
            for (int c = 0; c < CDIM; c++) qk += qs[il][c] * ks[c][j];
            float dist = 0.f;
            #pragma unroll
            for (int pd = 0; pd < 12; pd++) {
                float dlt = tqs[il][pd] - tks[pd][j];
                dist += dlt * dlt;
            }
            float lg = WL * (qk + brow[j] - coef * dist);
            lreg[jj] = lg;
            lmax = fmaxf(lmax, lg);
        }
        #pragma unroll
        for (int off = 16; off > 0; off >>= 1)
            lmax = fmaxf(lmax, __shfl_xor_sync(0xffffffffu, lmax, off));
        float s = 0.f;
        #pragma unroll
        for (int jj = 0; jj < 12; jj++) {
            float e = __expf(lreg[jj] - lmax);
            lreg[jj] = e;
            s += e;
        }
        #pragma unroll
        for (int off = 16; off > 0; off >>= 1)
            s += __shfl_xor_sync(0xffffffffu, s, off);
        float inv = 1.f / s;
        float* arow = &g_att[((size_t)h * N_RES + i) * N_RES];
        #pragma unroll
        for (int jj = 0; jj < 12; jj++)
            arow[lane + jj * 32] = lreg[jj] * inv;
    }
}

// ---------------- pairwise = einsum(z[i,j,c], att[h,i,j]) -> cat[i][576 + h*128 + c] ----------------
__device__ __forceinline__ float4 f4add(float4 a, float4 b) {
    return make_float4(a.x + b.x, a.y + b.y, a.z + b.z, a.w + b.w);
}
__global__ void pairwise_kernel(const float* __restrict__ z) {
    int i = blockIdx.x;
    int tid = threadIdx.x;   // 256
    __shared__ float att_s[N_HEAD][N_RES];   // 18 KB
    __shared__ float4 rbuf[4][N_HEAD][32];   // 24 KB
    for (int idx = tid; idx < N_HEAD * N_RES; idx += 256) {
        int h = idx / N_RES, j = idx % N_RES;
        att_s[h][j] = g_att[((size_t)h * N_RES + i) * N_RES + j];
    }
    __syncthreads();
    int c4 = tid & 31, jr = tid >> 5;  // 8 j-slices (one per warp), 32 float4 cols
    const float4* zp = (const float4*)(z + (size_t)i * N_RES * C_Z);
    float4 acc[N_HEAD];
    for (int h = 0; h < N_HEAD; h++) acc[h] = make_float4(0.f, 0.f, 0.f, 0.f);
    for (int j = jr; j < N_RES; j += 8) {
        float4 zv = zp[j * 32 + c4];
        #pragma unroll
        for (int h = 0; h < N_HEAD; h++) {
            float a = att_s[h][j];
            acc[h].x += a * zv.x; acc[h].y += a * zv.y;
            acc[h].z += a * zv.z; acc[h].w += a * zv.w;
        }
    }
    // tree reduce across the 8 warps
    if (jr >= 4) {
        for (int h = 0; h < N_HEAD; h++) rbuf[jr - 4][h][c4] = acc[h];
    }
    __syncthreads();
    if (jr < 4) {
        for (int h = 0; h < N_HEAD; h++) acc[h] = f4add(acc[h], rbuf[jr][h][c4]);
    }
    __syncthreads();
    if (jr == 2 || jr == 3) {
        for (int h = 0; h < N_HEAD; h++) rbuf[jr - 2][h][c4] = acc[h];
    }
    __syncthreads();
    if (jr < 2) {
        for (int h = 0; h < N_HEAD; h++) acc[h] = f4add(acc[h], rbuf[jr][h][c4]);
    }
    __syncthreads();
    if (jr == 1) {
        for (int h = 0; h < N_HEAD; h++) rbuf[0][h][c4] = acc[h];
    }
    __syncthreads();
    if (jr == 0) {
        #pragma unroll
        for (int h = 0; h < N_HEAD; h++) {
            float4 r = f4add(acc[h], rbuf[0][h][c4]);
            *((float4*)&g_cat[(size_t)i * 2112 + 576 + h * C_Z + c4 * 4]) = r;
        }
    }
}

// ---------------- eo[h][i][40] = att[h] @ vcat[h] ----------------
__global__ void vatt_kernel() {
    int h = blockIdx.y;
    int i0 = blockIdx.x * 32;
    __shared__ float at[32][33];
    __shared__ float vc[32][41];
    int tid = threadIdx.x;   // 320
    int col = tid % 40, rgrp = tid / 40;   // rgrp 0..7
    float acc[4] = {0.f, 0.f, 0.f, 0.f};
    for (int j0 = 0; j0 < N_RES; j0 += 32) {
        for (int idx = tid; idx < 1024; idx += 320) {
            int r = idx / 32, c = idx % 32;
            at[r][c] = g_att[((size_t)h * N_RES + i0 + r) * N_RES + j0 + c];
        }
        for (int idx = tid; idx < 1280; idx += 320) {
            int r = idx / 40, c = idx % 40;
            vc[r][c] = g_vcat[((size_t)h * N_RES + j0 + r) * 40 + c];
        }
        __syncthreads();
        #pragma unroll 8
        for (int jj = 0; jj < 32; jj++) {
            float b = vc[jj][col];
            #pragma unroll
            for (int rr = 0; rr < 4; rr++) acc[rr] += at[rgrp + rr * 8][jj] * b;
        }
        __syncthreads();
    }
    #pragma unroll
    for (int rr = 0; rr < 4; rr++)
        g_eo[((size_t)h * N_RES + i0 + rgrp + rr * 8) * 40 + col] = acc[rr];
}

// ---------------- inverse warp, norms, assemble cat cols [0,576) ----------------
__global__ void post_kernel(const float* __restrict__ T) {
    int t = blockIdx.x * blockDim.x + threadIdx.x;
    if (t >= N_HEAD * N_RES) return;
    int h = t / N_RES, i = t % N_RES;
    const float* e = &g_eo[(size_t)t * 40];
    float* catp = &g_cat[(size_t)i * 2112];
    #pragma unroll
    for (int c = 0; c < CDIM; c++) catp[h * CDIM + c] = e[c];
    float R[9], tv[3];
    #pragma unroll
    for (int d = 0; d < 9; d++) R[d] = T[i * 16 + (d / 3) * 4 + (d % 3)];
    #pragma unroll
    for (int d = 0; d < 3; d++) tv[d] = T[i * 16 + d * 4 + 3];
    #pragma unroll
    for (int k = 0; k < N_PV; k++) {
        float px = e[16 + k * 3 + 0] - tv[0];
        float py = e[16 + k * 3 + 1] - tv[1];
        float pz = e[16 + k * 3 + 2] - tv[2];
        float lx = R[0] * px + R[3] * py + R[6] * pz;
        float ly = R[1] * px + R[4] * py + R[7] * pz;
        float lz = R[2] * px + R[5] * py + R[8] * pz;
        catp[192 + 0 * 96 + h * N_PV + k] = lx;
        catp[192 + 1 * 96 + h * N_PV + k] = ly;
        catp[192 + 2 * 96 + h * N_PV + k] = lz;
        catp[480 + h * N_PV + k] = sqrtf(lx * lx + ly * ly + lz * lz);
    }
}

extern "C" void kernel_launch(void* const* d_in, const int* in_sizes, int n_in,
                              void* d_out, int out_size) {
    const float* s   = (const float*)d_in[0];
    const float* z   = (const float*)d_in[1];
    const float* T   = (const float*)d_in[2];
    const float* Wq  = (const float*)d_in[3];
    const float* bq  = (const float*)d_in[4];
    const float* Wk  = (const float*)d_in[5];
    const float* bk  = (const float*)d_in[6];
    const float* Wv  = (const float*)d_in[7];
    const float* bv  = (const float*)d_in[8];
    const float* Wqp = (const float*)d_in[9];
    const float* bqp = (const float*)d_in[10];
    const float* Wkp = (const float*)d_in[11];
    const float* bkp = (const float*)d_in[12];
    const float* Wvp = (const float*)d_in[13];
    const float* bvp = (const float*)d_in[14];
    const float* Wb  = (const float*)d_in[15];
    const float* bb  = (const float*)d_in[16];
    const float* Wo  = (const float*)d_in[17];
    const float* bo  = (const float*)d_in[18];
    const float* hw  = (const float*)d_in[19];
    float* out = (float*)d_out;

    float *p_proj, *p_Wcat, *p_bcat, *p_cat, *p_part;
    cudaGetSymbolAddress((void**)&p_proj, g_proj);
    cudaGetSymbolAddress((void**)&p_Wcat, g_Wcat);
    cudaGetSymbolAddress((void**)&p_bcat, g_bcat);
    cudaGetSymbolAddress((void**)&p_cat,  g_cat);
    cudaGetSymbolAddress((void**)&p_part, g_part);

    // 0) concat weights (1.8 MB, ~1us)
    prep_w<<<(C_S * NP + NP + 255) / 256, 256>>>(Wq, Wk, Wv, Wqp, Wkp, Wvp,
                                                 bq, bk, bv, bqp, bkp, bvp);
    // 1) all six projections in one GEMM: s(384x384) @ Wcat(384x1152)
    gemm64<<<dim3(NP / 64, N_RES / 64, 1), 256>>>(s, C_S, p_Wcat, NP, p_bcat, p_proj, NP, C_S);
    // 2) bias from z (75 MB stream)
    bias_kernel<<<(N_RES * N_RES) / 8, 256>>>(z, Wb, bb);
    // 3) frame transforms
    transform_kernel<<<N_RES, 128>>>(T);
    // 4) tiled attention + softmax
    attn_fused<<<dim3(N_RES / 32, N_HEAD), 256>>>(hw);
    // 5) pairwise (writes cat[576:2112)) — second 75 MB z stream
    pairwise_kernel<<<N_RES, 256>>>(z);
    // 6) att @ [v|vt]
    vatt_kernel<<<dim3(12, 12), 320>>>();
    // 7) inverse warp + norms + concat (writes cat[0:576))
    post_kernel<<<36, 128>>>(T);
    // 8) final projection: cat(384x2112) @ Wo(2112x384), split-K=4
    gemm64<<<dim3(C_S / 64, N_RES / 64, 4), 256>>>(p_cat, 2112, Wo, C_S, nullptr, p_part, C_S, 528);
    reduce_out<<<(N_RES * C_S / 4 + 255) / 256, 256>>>(bo, out);
}

// round 9
// speedup vs baseline: 2.3902x; 1.0466x over previous
#include <cuda_runtime.h>
#include <cuda_bf16.h>
#include <math.h>

#define N_RES 384
#define C_S   384
#define C_Z   128
#define N_HEAD 12
#define CDIM  16
#define N_QP  4
#define N_PV  8
#define NP    1152   // total projection output cols: 192*3 + 144*2 + 288
#define KSPLIT 6     // final GEMM split-K factor (2112 = 6*352, 352 = 11*32)

// ---------------- scratch (device globals; no allocation) ----------------
__device__ __align__(16) float g_proj[N_RES * NP];               // [i][1152]
__device__ __align__(16) float g_Wcat[C_S * NP];                 // concat weights
__device__ __align__(16) float g_bcat[NP];                       // concat biases
__device__ __align__(16) float g_tq [N_HEAD * N_QP * 3 * N_RES]; // [(h*4+p)*3+d][i]
__device__ __align__(16) float g_tk [N_HEAD * N_QP * 3 * N_RES];
__device__ __align__(16) float g_vcat[N_HEAD * N_RES * 40];      // [h][j][0:16 v, 16+k*3+d vt]
__device__ __align__(16) float g_bias[N_HEAD * N_RES * N_RES];   // [h][i][j]
__device__ __align__(16) float g_att [N_HEAD * N_RES * N_RES];   // [h][i][j]
__device__ __align__(16) float g_cat [N_RES * 2112];             // concat per residue
__device__ __align__(16) float g_part[KSPLIT * N_RES * C_S];     // split-K partials

// ---------------- prep: concat weights/biases into g_Wcat/g_bcat ----------------
__global__ void prep_w(const float* __restrict__ Wq, const float* __restrict__ Wk,
                       const float* __restrict__ Wv, const float* __restrict__ Wqp,
                       const float* __restrict__ Wkp, const float* __restrict__ Wvp,
                       const float* __restrict__ bq, const float* __restrict__ bk,
                       const float* __restrict__ bv, const float* __restrict__ bqp,
                       const float* __restrict__ bkp, const float* __restrict__ bvp) {
    int idx = blockIdx.x * blockDim.x + threadIdx.x;
    if (idx < C_S * NP) {
        int r = idx / NP, c = idx % NP;
        float w;
        if      (c < 192) w = Wq [r * 192 + c];
        else if (c < 384) w = Wk [r * 192 + c - 192];
        else if (c < 576) w = Wv [r * 192 + c - 384];
        else if (c < 720) w = Wqp[r * 144 + c - 576];
        else if (c < 864) w = Wkp[r * 144 + c - 720];
        else              w = Wvp[r * 288 + c - 864];
        g_Wcat[idx] = w;
    } else if (idx < C_S * NP + NP) {
        int c = idx - C_S * NP;
        float b;
        if      (c < 192) b = bq [c];
        else if (c < 384) b = bk [c - 192];
        else if (c < 576) b = bv [c - 384];
        else if (c < 720) b = bqp[c - 576];
        else if (c < 864) b = bkp[c - 720];
        else              b = bvp[c - 864];
        g_bcat[c] = b;
    }
}

// ---------------- tf32 helpers ----------------
__device__ __forceinline__ unsigned f2tf32(float f) {
    unsigned r;
    asm("cvt.rna.tf32.f32 %0, %1;" : "=r"(r) : "f"(f));
    return r;
}
__device__ __forceinline__ void mma_tf32(float* c, const unsigned* a, const unsigned* b) {
    asm("mma.sync.aligned.m16n8k8.row.col.f32.tf32.tf32.f32 "
        "{%0,%1,%2,%3}, {%4,%5,%6,%7}, {%8,%9}, {%0,%1,%2,%3};"
        : "+f"(c[0]), "+f"(c[1]), "+f"(c[2]), "+f"(c[3])
        : "r"(a[0]), "r"(a[1]), "r"(a[2]), "r"(a[3]), "r"(b[0]), "r"(b[1]));
}

// ---------------- tf32 GEMM (3xTF32): C = A(128-tile x K) @ B(K x 64-tile) ----------------
// M must be multiple of 128, N multiple of 64, kPerSplit multiple of 32.
__global__ void gemm_tf32(const float* __restrict__ A, int lda,
                          const float* __restrict__ B, int ldb,
                          const float* __restrict__ bias,
                          float* __restrict__ C, int ldc,
                          int kPerSplit) {
    __shared__ float As[128][36];   // [m][k], pad 36 (36%32==4 -> conflict-free frags)
    __shared__ float Bs[32][68];    // [k][n], pad 68
    int tid = threadIdx.x;          // 256
    int warp = tid >> 5, lane = tid & 31;
    int wm = (warp >> 1) * 32;      // warp m-offset (0..96)
    int wn = (warp & 1) * 32;       // warp n-offset (0/32)
    int row0 = blockIdx.y * 128, col0 = blockIdx.x * 64;
    int kb = blockIdx.z * kPerSplit;
    C += (size_t)blockIdx.z * N_RES * ldc;
    float acc[2][4][4] = {};
    int lm = lane >> 2, lk = lane & 3;
    for (int kt = 0; kt < kPerSplit; kt += 32) {
        // load A 128x32
        #pragma unroll
        for (int l = 0; l < 4; l++) {
            int idx = tid + l * 256;             // 1024 float4
            int r = idx >> 3, kc = (idx & 7) * 4;
            float4 a4 = *(const float4*)&A[(size_t)(row0 + r) * lda + kb + kt + kc];
            *(float4*)&As[r][kc] = a4;
        }
        // load B 32x64
        #pragma unroll
        for (int l = 0; l < 2; l++) {
            int idx = tid + l * 256;             // 512 float4
            int r = idx >> 4, nc = (idx & 15) * 4;
            float4 b4 = *(const float4*)&B[(size_t)(kb + kt + r) * ldb + col0 + nc];
            *(float4*)&Bs[r][nc] = b4;
        }
        __syncthreads();
        #pragma unroll
        for (int k8 = 0; k8 < 32; k8 += 8) {
            unsigned ah[2][4], al[2][4], bh[4][2], bl[4][2];
            #pragma unroll
            for (int mf = 0; mf < 2; mf++) {
                int m = wm + mf * 16 + lm;
                float v0 = As[m][k8 + lk];
                float v1 = As[m + 8][k8 + lk];
                float v2 = As[m][k8 + 4 + lk];
                float v3 = As[m + 8][k8 + 4 + lk];
                ah[mf][0] = f2tf32(v0); al[mf][0] = f2tf32(v0 - __uint_as_float(ah[mf][0]));
                ah[mf][1] = f2tf32(v1); al[mf][1] = f2tf32(v1 - __uint_as_float(ah[mf][1]));
                ah[mf][2] = f2tf32(v2); al[mf][2] = f2tf32(v2 - __uint_as_float(ah[mf][2]));
                ah[mf][3] = f2tf32(v3); al[mf][3] = f2tf32(v3 - __uint_as_float(ah[mf][3]));
            }
            #pragma unroll
            for (int nf = 0; nf < 4; nf++) {
                int n = wn + nf * 8 + lm;
                float w0 = Bs[k8 + lk][n];
                float w1 = Bs[k8 + 4 + lk][n];
                bh[nf][0] = f2tf32(w0); bl[nf][0] = f2tf32(w0 - __uint_as_float(bh[nf][0]));
                bh[nf][1] = f2tf32(w1); bl[nf][1] = f2tf32(w1 - __uint_as_float(bh[nf][1]));
            }
            #pragma unroll
            for (int mf = 0; mf < 2; mf++) {
                #pragma unroll
                for (int nf = 0; nf < 4; nf++) {
                    mma_tf32(acc[mf][nf], al[mf], bh[nf]);
                    mma_tf32(acc[mf][nf], ah[mf], bl[nf]);
                    mma_tf32(acc[mf][nf], ah[mf], bh[nf]);
                }
            }
        }
        __syncthreads();
    }
    // epilogue
    #pragma unroll
    for (int mf = 0; mf < 2; mf++) {
        #pragma unroll
        for (int nf = 0; nf < 4; nf++) {
            int r = row0 + wm + mf * 16 + lm;
            int c = col0 + wn + nf * 8 + lk * 2;
            float2 v0 = make_float2(acc[mf][nf][0], acc[mf][nf][1]);
            float2 v1 = make_float2(acc[mf][nf][2], acc[mf][nf][3]);
            if (bias != nullptr) {
                float b0 = bias[c], b1 = bias[c + 1];
                v0.x += b0; v0.y += b1; v1.x += b0; v1.y += b1;
            }
            *(float2*)&C[(size_t)r * ldc + c] = v0;
            *(float2*)&C[(size_t)(r + 8) * ldc + c] = v1;
        }
    }
}

// ---------------- reduce split-K partials + bias -> out ----------------
__global__ void reduce_out(const float* __restrict__ bo, float* __restrict__ out) {
    int idx = blockIdx.x * blockDim.x + threadIdx.x;  // over 36864 float4
    if (idx >= N_RES * C_S / 4) return;
    const float4* p = (const float4*)g_part;
    float4 r = p[idx];
    #pragma unroll
    for (int s = 1; s < KSPLIT; s++) {
        float4 q = p[idx + s * (N_RES * C_S / 4)];
        r.x += q.x; r.y += q.y; r.z += q.z; r.w += q.w;
    }
    int col = (idx * 4) % C_S;
    r.x += bo[col]; r.y += bo[col + 1]; r.z += bo[col + 2]; r.w += bo[col + 3];
    ((float4*)out)[idx] = r;
}

// ---------------- bias = moveaxis(z @ Wb + bb): [h][i][j] ----------------
__global__ void bias_kernel(const float* __restrict__ z, const float* __restrict__ Wb,
                            const float* __restrict__ bb) {
    __shared__ float wbs[C_Z * N_HEAD];
    __shared__ float bbs[N_HEAD];
    int tid = threadIdx.x;   // 256
    for (int i = tid; i < C_Z * N_HEAD; i += 256) wbs[i] = Wb[i];
    if (tid < N_HEAD) bbs[tid] = bb[tid];
    __syncthreads();
    int warp = tid >> 5, lane = tid & 31;
    int row = blockIdx.x * 8 + warp;                 // flattened (i,j)
    if (row >= N_RES * N_RES) return;
    float4 z4 = ((const float4*)(z + (size_t)row * C_Z))[lane];
    float part[N_HEAD];
    int cb = lane * 4;
    #pragma unroll
    for (int h = 0; h < N_HEAD; h++) {
        part[h] = z4.x * wbs[(cb + 0) * N_HEAD + h] + z4.y * wbs[(cb + 1) * N_HEAD + h]
                + z4.z * wbs[(cb + 2) * N_HEAD + h] + z4.w * wbs[(cb + 3) * N_HEAD + h];
    }
    #pragma unroll
    for (int off = 16; off > 0; off >>= 1) {
        #pragma unroll
        for (int h = 0; h < N_HEAD; h++)
            part[h] += __shfl_down_sync(0xffffffffu, part[h], off);
    }
    if (lane == 0) {
        #pragma unroll
        for (int h = 0; h < N_HEAD; h++)
            g_bias[(size_t)h * (N_RES * N_RES) + row] = part[h] + bbs[h];
    }
}

// ---------------- transform points with frames; build tq/tk SoA + vcat ----------------
__global__ void transform_kernel(const float* __restrict__ T) {
    int i = blockIdx.x;
    int tid = threadIdx.x;   // 128
    __shared__ float Rm[9], tv[3];
    if (tid < 9) Rm[tid] = T[i * 16 + (tid / 3) * 4 + (tid % 3)];
    if (tid < 3) tv[tid] = T[i * 16 + tid * 4 + 3];
    __syncthreads();
    const float* prow = &g_proj[(size_t)i * NP];
    // q / k points: 48 each
    if (tid < 96) {
        int set = tid / 48, hp = tid % 48;
        int base = set ? 720 : 576;
        float lx = prow[base + 0 * 48 + hp];
        float ly = prow[base + 1 * 48 + hp];
        float lz = prow[base + 2 * 48 + hp];
        float gx = Rm[0] * lx + Rm[1] * ly + Rm[2] * lz + tv[0];
        float gy = Rm[3] * lx + Rm[4] * ly + Rm[5] * lz + tv[1];
        float gz = Rm[6] * lx + Rm[7] * ly + Rm[8] * lz + tv[2];
        float* dst = set ? g_tk : g_tq;
        dst[(hp * 3 + 0) * N_RES + i] = gx;
        dst[(hp * 3 + 1) * N_RES + i] = gy;
        dst[(hp * 3 + 2) * N_RES + i] = gz;
    }
    // v points: 96
    if (tid < 96) {
        int hp = tid;                 // h*8 + k
        float lx = prow[864 + 0 * 96 + hp];
        float ly = prow[864 + 1 * 96 + hp];
        float lz = prow[864 + 2 * 96 + hp];
        float gx = Rm[0] * lx + Rm[1] * ly + Rm[2] * lz + tv[0];
        float gy = Rm[3] * lx + Rm[4] * ly + Rm[5] * lz + tv[1];
        float gz = Rm[6] * lx + Rm[7] * ly + Rm[8] * lz + tv[2];
        int h = hp / 8, k = hp % 8;
        float* d = &g_vcat[((size_t)h * N_RES + i) * 40 + 16 + k * 3];
        d[0] = gx; d[1] = gy; d[2] = gz;
    }
    // copy v into vcat cols 0..15
    for (int c = tid; c < N_HEAD * CDIM; c += 128) {
        int h = c / CDIM, cc = c % CDIM;
        g_vcat[((size_t)h * N_RES + i) * 40 + cc] = prow[384 + c];
    }
}

// ---------------- tiled attention: block per (h, 32-row i-tile) ----------------
__global__ void attn_fused(const float* __restrict__ hw) {
    const float WL  = 0.5773502691896258f;   // sqrt(1/3)
    const float WC2 = 0.11785113019775793f;  // sqrt(2/(9*4))/2
    int h = blockIdx.y;
    int i0 = blockIdx.x * 32;
    int tid = threadIdx.x;   // 256
    __shared__ float ks [CDIM][N_RES];       // 24 KB
    __shared__ float tks[12][N_RES];         // 18 KB
    __shared__ float qs [32][CDIM];          // 2 KB
    __shared__ float tqs[32][12];            // 1.5 KB
    for (int t = tid; t < N_RES * 4; t += 256) {
        int j = t >> 2, cq = (t & 3) * 4;
        float4 kv = *(const float4*)&g_proj[(size_t)j * NP + 192 + h * CDIM + cq];
        ks[cq + 0][j] = kv.x; ks[cq + 1][j] = kv.y;
        ks[cq + 2][j] = kv.z; ks[cq + 3][j] = kv.w;
    }
    for (int t = tid; t < 12 * N_RES; t += 256) tks[t / N_RES][t % N_RES] = g_tk[h * 12 * N_RES + t];
    for (int t = tid; t < 32 * CDIM; t += 256) {
        int il = t / CDIM, c = t % CDIM;
        qs[il][c] = g_proj[(size_t)(i0 + il) * NP + h * CDIM + c] * 0.25f;  // 1/sqrt(C)
    }
    for (int t = tid; t < 32 * 12; t += 256) {
        int il = t / 12, pd = t % 12;
        tqs[il][pd] = g_tq[(h * 12 + pd) * N_RES + i0 + il];
    }
    __syncthreads();
    float gam = log1pf(__expf(hw[h]));
    float coef = gam * WC2;
    int w = tid >> 5, lane = tid & 31;
    #pragma unroll
    for (int rr = 0; rr < 4; rr++) {
        int il = w * 4 + rr;
        int i = i0 + il;
        const float* brow = &g_bias[((size_t)h * N_RES + i) * N_RES];
        float lreg[12];
        float lmax = -1e30f;
        #pragma unroll
        for (int jj = 0; jj < 12; jj++) {
            int j = lane + jj * 32;
            float qk = 0.f;
            #pragma unroll
            for (int c = 0; c < CDIM; c++) qk += qs[il][c] * ks[c][j];
            float dist = 0.f;
            #pragma unroll
            for (int pd = 0; pd < 12; pd++) {
                float dlt = tqs[il][pd] - tks[pd][j];
                dist += dlt * dlt;
            }
            float lg = WL * (qk + brow[j] - coef * dist);
            lreg[jj] = lg;
            lmax = fmaxf(lmax, lg);
        }
        #pragma unroll
        for (int off = 16; off > 0; off >>= 1)
            lmax = fmaxf(lmax, __shfl_xor_sync(0xffffffffu, lmax, off));
        float s = 0.f;
        #pragma unroll
        for (int jj = 0; jj < 12; jj++) {
            float e = __expf(lreg[jj] - lmax);
            lreg[jj] = e;
            s += e;
        }
        #pragma unroll
        for (int off = 16; off > 0; off >>= 1)
            s += __shfl_xor_sync(0xffffffffu, s, off);
        float inv = 1.f / s;
        float* arow = &g_att[((size_t)h * N_RES + i) * N_RES];
        #pragma unroll
        for (int jj = 0; jj < 12; jj++)
            arow[lane + jj * 32] = lreg[jj] * inv;
    }
}

// ---------------- pairwise = einsum(z[i,j,c], att[h,i,j]) -> cat[i][576 + h*128 + c] ----------------
__device__ __forceinline__ float4 f4add(float4 a, float4 b) {
    return make_float4(a.x + b.x, a.y + b.y, a.z + b.z, a.w + b.w);
}
__global__ void pairwise_kernel(const float* __restrict__ z) {
    int i = blockIdx.x;
    int tid = threadIdx.x;   // 256
    __shared__ float att_s[N_HEAD][N_RES];   // 18 KB
    __shared__ float4 rbuf[4][N_HEAD][32];   // 24 KB
    for (int idx = tid; idx < N_HEAD * N_RES; idx += 256) {
        int h = idx / N_RES, j = idx % N_RES;
        att_s[h][j] = g_att[((size_t)h * N_RES + i) * N_RES + j];
    }
    __syncthreads();
    int c4 = tid & 31, jr = tid >> 5;
    const float4* zp = (const float4*)(z + (size_t)i * N_RES * C_Z);
    float4 acc[N_HEAD];
    for (int h = 0; h < N_HEAD; h++) acc[h] = make_float4(0.f, 0.f, 0.f, 0.f);
    for (int j = jr; j < N_RES; j += 8) {
        float4 zv = zp[j * 32 + c4];
        #pragma unroll
        for (int h = 0; h < N_HEAD; h++) {
            float a = att_s[h][j];
            acc[h].x += a * zv.x; acc[h].y += a * zv.y;
            acc[h].z += a * zv.z; acc[h].w += a * zv.w;
        }
    }
    if (jr >= 4) {
        for (int h = 0; h < N_HEAD; h++) rbuf[jr - 4][h][c4] = acc[h];
    }
    __syncthreads();
    if (jr < 4) {
        for (int h = 0; h < N_HEAD; h++) acc[h] = f4add(acc[h], rbuf[jr][h][c4]);
    }
    __syncthreads();
    if (jr == 2 || jr == 3) {
        for (int h = 0; h < N_HEAD; h++) rbuf[jr - 2][h][c4] = acc[h];
    }
    __syncthreads();
    if (jr < 2) {
        for (int h = 0; h < N_HEAD; h++) acc[h] = f4add(acc[h], rbuf[jr][h][c4]);
    }
    __syncthreads();
    if (jr == 1) {
        for (int h = 0; h < N_HEAD; h++) rbuf[0][h][c4] = acc[h];
    }
    __syncthreads();
    if (jr == 0) {
        #pragma unroll
        for (int h = 0; h < N_HEAD; h++) {
            float4 r = f4add(acc[h], rbuf[0][h][c4]);
            *((float4*)&g_cat[(size_t)i * 2112 + 576 + h * C_Z + c4 * 4]) = r;
        }
    }
}

// ---------------- eo = att[h] @ vcat[h], fused with inverse warp/norm/concat ----------------
__global__ void vatt_post(const float* __restrict__ T) {
    int h = blockIdx.y;
    int i0 = blockIdx.x * 32;
    __shared__ float at[32][33];
    __shared__ float vc[32][41];
    __shared__ float eo_s[32][41];
    int tid = threadIdx.x;   // 320
    int col = tid % 40, rgrp = tid / 40;   // rgrp 0..7
    float acc[4] = {0.f, 0.f, 0.f, 0.f};
    for (int j0 = 0; j0 < N_RES; j0 += 32) {
        for (int idx = tid; idx < 1024; idx += 320) {
            int r = idx / 32, c = idx % 32;
            at[r][c] = g_att[((size_t)h * N_RES + i0 + r) * N_RES + j0 + c];
        }
        for (int idx = tid; idx < 1280; idx += 320) {
            int r = idx / 40, c = idx % 40;
            vc[r][c] = g_vcat[((size_t)h * N_RES + j0 + r) * 40 + c];
        }
        __syncthreads();
        #pragma unroll 8
        for (int jj = 0; jj < 32; jj++) {
            float b = vc[jj][col];
            #pragma unroll
            for (int rr = 0; rr < 4; rr++) acc[rr] += at[rgrp + rr * 8][jj] * b;
        }
        __syncthreads();
    }
    #pragma unroll
    for (int rr = 0; rr < 4; rr++)
        eo_s[rgrp + rr * 8][col] = acc[rr];
    __syncthreads();
    // fused post: one thread per local row
    if (tid < 32) {
        int i = i0 + tid;
        const float* e = eo_s[tid];
        float* catp = &g_cat[(size_t)i * 2112];
        #pragma unroll
        for (int c = 0; c < CDIM; c++) catp[h * CDIM + c] = e[c];
        float R[9], tv[3];
        #pragma unroll
        for (int d = 0; d < 9; d++) R[d] = T[i * 16 + (d / 3) * 4 + (d % 3)];
        #pragma unroll
        for (int d = 0; d < 3; d++) tv[d] = T[i * 16 + d * 4 + 3];
        #pragma unroll
        for (int k = 0; k < N_PV; k++) {
            float px = e[16 + k * 3 + 0] - tv[0];
            float py = e[16 + k * 3 + 1] - tv[1];
            float pz = e[16 + k * 3 + 2] - tv[2];
            float lx = R[0] * px + R[3] * py + R[6] * pz;
            float ly = R[1] * px + R[4] * py + R[7] * pz;
            float lz = R[2] * px + R[5] * py + R[8] * pz;
            catp[192 + 0 * 96 + h * N_PV + k] = lx;
            catp[192 + 1 * 96 + h * N_PV + k] = ly;
            catp[192 + 2 * 96 + h * N_PV + k] = lz;
            catp[480 + h * N_PV + k] = sqrtf(lx * lx + ly * ly + lz * lz);
        }
    }
}

extern "C" void kernel_launch(void* const* d_in, const int* in_sizes, int n_in,
                              void* d_out, int out_size) {
    const float* s   = (const float*)d_in[0];
    const float* z   = (const float*)d_in[1];
    const float* T   = (const float*)d_in[2];
    const float* Wq  = (const float*)d_in[3];
    const float* bq  = (const float*)d_in[4];
    const float* Wk  = (const float*)d_in[5];
    const float* bk  = (const float*)d_in[6];
    const float* Wv  = (const float*)d_in[7];
    const float* bv  = (const float*)d_in[8];
    const float* Wqp = (const float*)d_in[9];
    const float* bqp = (const float*)d_in[10];
    const float* Wkp = (const float*)d_in[11];
    const float* bkp = (const float*)d_in[12];
    const float* Wvp = (const float*)d_in[13];
    const float* bvp = (const float*)d_in[14];
    const float* Wb  = (const float*)d_in[15];
    const float* bb  = (const float*)d_in[16];
    const float* Wo  = (const float*)d_in[17];
    const float* bo  = (const float*)d_in[18];
    const float* hw  = (const float*)d_in[19];
    float* out = (float*)d_out;

    float *p_proj, *p_Wcat, *p_bcat, *p_cat, *p_part;
    cudaGetSymbolAddress((void**)&p_proj, g_proj);
    cudaGetSymbolAddress((void**)&p_Wcat, g_Wcat);
    cudaGetSymbolAddress((void**)&p_bcat, g_bcat);
    cudaGetSymbolAddress((void**)&p_cat,  g_cat);
    cudaGetSymbolAddress((void**)&p_part, g_part);

    // 0) concat weights
    prep_w<<<(C_S * NP + NP + 255) / 256, 256>>>(Wq, Wk, Wv, Wqp, Wkp, Wvp,
                                                 bq, bk, bv, bqp, bkp, bvp);
    // 1) all six projections in one tf32 GEMM: s(384x384) @ Wcat(384x1152)
    gemm_tf32<<<dim3(NP / 64, N_RES / 128, 1), 256>>>(s, C_S, p_Wcat, NP, p_bcat, p_proj, NP, C_S);
    // 2) bias from z (75 MB stream)
    bias_kernel<<<(N_RES * N_RES) / 8, 256>>>(z, Wb, bb);
    // 3) frame transforms
    transform_kernel<<<N_RES, 128>>>(T);
    // 4) tiled attention + softmax
    attn_fused<<<dim3(N_RES / 32, N_HEAD), 256>>>(hw);
    // 5) pairwise (writes cat[576:2112)) — second 75 MB z stream
    pairwise_kernel<<<N_RES, 256>>>(z);
    // 6) att @ [v|vt]  + fused inverse warp/norm/concat (writes cat[0:576))
    vatt_post<<<dim3(12, 12), 320>>>(T);
    // 7) final projection: cat(384x2112) @ Wo(2112x384), tf32 split-K=6
    gemm_tf32<<<dim3(C_S / 64, N_RES / 128, KSPLIT), 256>>>(p_cat, 2112, Wo, C_S, nullptr, p_part, C_S, 2112 / KSPLIT);
    reduce_out<<<(N_RES * C_S / 4 + 255) / 256, 256>>>(bo, out);
}

// round 11
// speedup vs baseline: 2.5341x; 1.0602x over previous
#include <cuda_runtime.h>
#include <cuda_bf16.h>
#include <math.h>

#define N_RES 384
#define C_S   384
#define C_Z   128
#define N_HEAD 12
#define CDIM  16
#define N_QP  4
#define N_PV  8
#define NP    1152   // total projection output cols: 192*3 + 144*2 + 288
#define KSPLIT 6     // final GEMM split-K factor (2112 = 6*352, 352 = 11*32)
#define NROWS (N_RES * N_RES)

// ---------------- scratch (device globals; no allocation) ----------------
__device__ __align__(16) float g_proj[N_RES * NP];               // [i][1152]
__device__ __align__(16) float g_Wcat[C_S * NP];                 // concat weights
__device__ __align__(16) float g_bcat[NP];                       // concat biases
__device__ __align__(16) float g_wbhi[C_Z * 16];                 // Wb tf32-hi, [k][n16]
__device__ __align__(16) float g_wblo[C_Z * 16];                 // Wb tf32-lo
__device__ __align__(16) float g_tq [N_HEAD * N_QP * 3 * N_RES]; // [(h*4+p)*3+d][i]
__device__ __align__(16) float g_tk [N_HEAD * N_QP * 3 * N_RES];
__device__ __align__(16) float g_vcat[N_HEAD * N_RES * 40];      // [h][j][0:16 v, 16+k*3+d vt]
__device__ __align__(16) float g_bias[N_HEAD * NROWS];           // [h][i][j]
__device__ __align__(16) float g_att [N_HEAD * NROWS];           // [h][i][j]
__device__ __align__(16) float g_cat [N_RES * 2112];             // concat per residue
__device__ __align__(16) float g_part[KSPLIT * N_RES * C_S];     // split-K partials

// ---------------- tf32 helpers ----------------
__device__ __forceinline__ unsigned f2tf32(float f) {
    unsigned r;
    asm("cvt.rna.tf32.f32 %0, %1;" : "=r"(r) : "f"(f));
    return r;
}
__device__ __forceinline__ void mma_tf32(float* c, const unsigned* a, const unsigned* b) {
    asm("mma.sync.aligned.m16n8k8.row.col.f32.tf32.tf32.f32 "
        "{%0,%1,%2,%3}, {%4,%5,%6,%7}, {%8,%9}, {%0,%1,%2,%3};"
        : "+f"(c[0]), "+f"(c[1]), "+f"(c[2]), "+f"(c[3])
        : "r"(a[0]), "r"(a[1]), "r"(a[2]), "r"(a[3]), "r"(b[0]), "r"(b[1]));
}

// ---------------- prep: concat weights/biases; split Wb into tf32 hi/lo ----------------
__global__ void prep_w(const float* __restrict__ Wq, const float* __restrict__ Wk,
                       const float* __restrict__ Wv, const float* __restrict__ Wqp,
                       const float* __restrict__ Wkp, const float* __restrict__ Wvp,
                       const float* __restrict__ bq, const float* __restrict__ bk,
                       const float* __restrict__ bv, const float* __restrict__ bqp,
                       const float* __restrict__ bkp, const float* __restrict__ bvp,
                       const float* __restrict__ Wb) {
    int idx = blockIdx.x * blockDim.x + threadIdx.x;
    if (idx < C_S * NP) {
        int r = idx / NP, c = idx % NP;
        float w;
        if      (c < 192) w = Wq [r * 192 + c];
        else if (c < 384) w = Wk [r * 192 + c - 192];
        else if (c < 576) w = Wv [r * 192 + c - 384];
        else if (c < 720) w = Wqp[r * 144 + c - 576];
        else if (c < 864) w = Wkp[r * 144 + c - 720];
        else              w = Wvp[r * 288 + c - 864];
        g_Wcat[idx] = w;
    } else if (idx < C_S * NP + NP) {
        int c = idx - C_S * NP;
        float b;
        if      (c < 192) b = bq [c];
        else if (c < 384) b = bk [c - 192];
        else if (c < 576) b = bv [c - 384];
        else if (c < 720) b = bqp[c - 576];
        else if (c < 864) b = bkp[c - 720];
        else              b = bvp[c - 864];
        g_bcat[c] = b;
    } else if (idx < C_S * NP + NP + C_Z * 16) {
        int e = idx - (C_S * NP + NP);
        int k = e >> 4, n = e & 15;
        float w = (n < N_HEAD) ? Wb[k * N_HEAD + n] : 0.f;
        float hi = __uint_as_float(f2tf32(w));
        g_wbhi[e] = hi;
        g_wblo[e] = __uint_as_float(f2tf32(w - hi));
    }
}

// ---------------- tf32 GEMM (3xTF32): C = A(128-tile x K) @ B(K x 64-tile) ----------------
__global__ void gemm_tf32(const float* __restrict__ A, int lda,
                          const float* __restrict__ B, int ldb,
                          const float* __restrict__ bias,
                          float* __restrict__ C, int ldc,
                          int kPerSplit) {
    __shared__ float As[128][36];
    __shared__ float Bs[32][68];
    int tid = threadIdx.x;          // 256
    int warp = tid >> 5, lane = tid & 31;
    int wm = (warp >> 1) * 32;
    int wn = (warp & 1) * 32;
    int row0 = blockIdx.y * 128, col0 = blockIdx.x * 64;
    int kb = blockIdx.z * kPerSplit;
    C += (size_t)blockIdx.z * N_RES * ldc;
    float acc[2][4][4] = {};
    int lm = lane >> 2, lk = lane & 3;
    for (int kt = 0; kt < kPerSplit; kt += 32) {
        #pragma unroll
        for (int l = 0; l < 4; l++) {
            int idx = tid + l * 256;
            int r = idx >> 3, kc = (idx & 7) * 4;
            float4 a4 = *(const float4*)&A[(size_t)(row0 + r) * lda + kb + kt + kc];
            *(float4*)&As[r][kc] = a4;
        }
        #pragma unroll
        for (int l = 0; l < 2; l++) {
            int idx = tid + l * 256;
            int r = idx >> 4, nc = (idx & 15) * 4;
            float4 b4 = *(const float4*)&B[(size_t)(kb + kt + r) * ldb + col0 + nc];
            *(float4*)&Bs[r][nc] = b4;
        }
        __syncthreads();
        #pragma unroll
        for (int k8 = 0; k8 < 32; k8 += 8) {
            unsigned ah[2][4], al[2][4], bh[4][2], bl[4][2];
            #pragma unroll
            for (int mf = 0; mf < 2; mf++) {
                int m = wm + mf * 16 + lm;
                float v0 = As[m][k8 + lk];
                float v1 = As[m + 8][k8 + lk];
                float v2 = As[m][k8 + 4 + lk];
                float v3 = As[m + 8][k8 + 4 + lk];
                ah[mf][0] = f2tf32(v0); al[mf][0] = f2tf32(v0 - __uint_as_float(ah[mf][0]));
                ah[mf][1] = f2tf32(v1); al[mf][1] = f2tf32(v1 - __uint_as_float(ah[mf][1]));
                ah[mf][2] = f2tf32(v2); al[mf][2] = f2tf32(v2 - __uint_as_float(ah[mf][2]));
                ah[mf][3] = f2tf32(v3); al[mf][3] = f2tf32(v3 - __uint_as_float(ah[mf][3]));
            }
            #pragma unroll
            for (int nf = 0; nf < 4; nf++) {
                int n = wn + nf * 8 + lm;
                float w0 = Bs[k8 + lk][n];
                float w1 = Bs[k8 + 4 + lk][n];
                bh[nf][0] = f2tf32(w0); bl[nf][0] = f2tf32(w0 - __uint_as_float(bh[nf][0]));
                bh[nf][1] = f2tf32(w1); bl[nf][1] = f2tf32(w1 - __uint_as_float(bh[nf][1]));
            }
            #pragma unroll
            for (int mf = 0; mf < 2; mf++) {
                #pragma unroll
                for (int nf = 0; nf < 4; nf++) {
                    mma_tf32(acc[mf][nf], al[mf], bh[nf]);
                    mma_tf32(acc[mf][nf], ah[mf], bl[nf]);
                    mma_tf32(acc[mf][nf], ah[mf], bh[nf]);
                }
            }
        }
        __syncthreads();
    }
    #pragma unroll
    for (int mf = 0; mf < 2; mf++) {
        #pragma unroll
        for (int nf = 0; nf < 4; nf++) {
            int r = row0 + wm + mf * 16 + lm;
            int c = col0 + wn + nf * 8 + lk * 2;
            float2 v0 = make_float2(acc[mf][nf][0], acc[mf][nf][1]);
            float2 v1 = make_float2(acc[mf][nf][2], acc[mf][nf][3]);
            if (bias != nullptr) {
                float b0 = bias[c], b1 = bias[c + 1];
                v0.x += b0; v0.y += b1; v1.x += b0; v1.y += b1;
            }
            *(float2*)&C[(size_t)r * ldc + c] = v0;
            *(float2*)&C[(size_t)(r + 8) * ldc + c] = v1;
        }
    }
}

// ---------------- reduce split-K partials + bias -> out ----------------
__global__ void reduce_out(const float* __restrict__ bo, float* __restrict__ out) {
    int idx = blockIdx.x * blockDim.x + threadIdx.x;
    if (idx >= N_RES * C_S / 4) return;
    const float4* p = (const float4*)g_part;
    float4 r = p[idx];
    #pragma unroll
    for (int s = 1; s < KSPLIT; s++) {
        float4 q = p[idx + s * (N_RES * C_S / 4)];
        r.x += q.x; r.y += q.y; r.z += q.z; r.w += q.w;
    }
    int col = (idx * 4) % C_S;
    r.x += bo[col]; r.y += bo[col + 1]; r.z += bo[col + 2]; r.w += bo[col + 3];
    ((float4*)out)[idx] = r;
}

// ---------------- bias = moveaxis(z @ Wb + bb) via m16n8k8 3xTF32 ----------------
// M = 147456 flattened (i,j) rows, K = 128, N = 16 (12 used). 1152 blocks x 128 rows.
__global__ void bias_mma(const float* __restrict__ z, const float* __restrict__ bb) {
    __shared__ float bhs[C_Z][16];     // 8 KB
    __shared__ float bls[C_Z][16];     // 8 KB
    __shared__ float cbuf[128][17];    // 8.5 KB (pad 17: conflict-free col reads)
    int tid = threadIdx.x;             // 256
    for (int e = tid; e < C_Z * 16; e += 256) {
        bhs[e >> 4][e & 15] = g_wbhi[e];
        bls[e >> 4][e & 15] = g_wblo[e];
    }
    __syncthreads();
    int warp = tid >> 5, lane = tid & 31;
    int lm = lane >> 2, lk = lane & 3;
    int row0 = blockIdx.x * 128 + warp * 16;
    const float* zr0 = z + (size_t)(row0 + lm) * C_Z;
    const float* zr1 = z + (size_t)(row0 + lm + 8) * C_Z;
    float acc[2][4] = {};
    #pragma unroll
    for (int k8 = 0; k8 < C_Z; k8 += 8) {
        float a0f = zr0[k8 + lk];
        float a1f = zr1[k8 + lk];
        float a2f = zr0[k8 + 4 + lk];
        float a3f = zr1[k8 + 4 + lk];
        unsigned ah[4], al[4];
        ah[0] = f2tf32(a0f); al[0] = f2tf32(a0f - __uint_as_float(ah[0]));
        ah[1] = f2tf32(a1f); al[1] = f2tf32(a1f - __uint_as_float(ah[1]));
        ah[2] = f2tf32(a2f); al[2] = f2tf32(a2f - __uint_as_float(ah[2]));
        ah[3] = f2tf32(a3f); al[3] = f2tf32(a3f - __uint_as_float(ah[3]));
        #pragma unroll
        for (int g = 0; g < 2; g++) {
            unsigned bhf[2], blf[2];
            bhf[0] = __float_as_uint(bhs[k8 + lk][g * 8 + lm]);
            bhf[1] = __float_as_uint(bhs[k8 + 4 + lk][g * 8 + lm]);
            blf[0] = __float_as_uint(bls[k8 + lk][g * 8 + lm]);
            blf[1] = __float_as_uint(bls[k8 + 4 + lk][g * 8 + lm]);
            mma_tf32(acc[g], al, bhf);
            mma_tf32(acc[g], ah, blf);
            mma_tf32(acc[g], ah, bhf);
        }
    }
    #pragma unroll
    for (int g = 0; g < 2; g++) {
        cbuf[warp * 16 + lm][g * 8 + lk * 2]         = acc[g][0];
        cbuf[warp * 16 + lm][g * 8 + lk * 2 + 1]     = acc[g][1];
        cbuf[warp * 16 + lm + 8][g * 8 + lk * 2]     = acc[g][2];
        cbuf[warp * 16 + lm + 8][g * 8 + lk * 2 + 1] = acc[g][3];
    }
    __syncthreads();
    int base = blockIdx.x * 128;
    for (int e = tid; e < N_HEAD * 128; e += 256) {
        int h = e >> 7, r = e & 127;
        g_bias[(size_t)h * NROWS + base + r] = cbuf[r][h] + bb[h];
    }
}

// ---------------- transform points with frames; build tq/tk SoA + vcat ----------------
__global__ void transform_kernel(const float* __restrict__ T) {
    int i = blockIdx.x;
    int tid = threadIdx.x;   // 128
    __shared__ float Rm[9], tv[3];
    if (tid < 9) Rm[tid] = T[i * 16 + (tid / 3) * 4 + (tid % 3)];
    if (tid < 3) tv[tid] = T[i * 16 + tid * 4 + 3];
    __syncthreads();
    const float* prow = &g_proj[(size_t)i * NP];
    if (tid < 96) {
        int set = tid / 48, hp = tid % 48;
        int base = set ? 720 : 576;
        float lx = prow[base + 0 * 48 + hp];
        float ly = prow[base + 1 * 48 + hp];
        float lz = prow[base + 2 * 48 + hp];
        float gx = Rm[0] * lx + Rm[1] * ly + Rm[2] * lz + tv[0];
        float gy = Rm[3] * lx + Rm[4] * ly + Rm[5] * lz + tv[1];
        float gz = Rm[6] * lx + Rm[7] * ly + Rm[8] * lz + tv[2];
        float* dst = set ? g_tk : g_tq;
        dst[(hp * 3 + 0) * N_RES + i] = gx;
        dst[(hp * 3 + 1) * N_RES + i] = gy;
        dst[(hp * 3 + 2) * N_RES + i] = gz;
    }
    if (tid < 96) {
        int hp = tid;
        float lx = prow[864 + 0 * 96 + hp];
        float ly = prow[864 + 1 * 96 + hp];
        float lz = prow[864 + 2 * 96 + hp];
        float gx = Rm[0] * lx + Rm[1] * ly + Rm[2] * lz + tv[0];
        float gy = Rm[3] * lx + Rm[4] * ly + Rm[5] * lz + tv[1];
        float gz = Rm[6] * lx + Rm[7] * ly + Rm[8] * lz + tv[2];
        int h = hp / 8, k = hp % 8;
        float* d = &g_vcat[((size_t)h * N_RES + i) * 40 + 16 + k * 3];
        d[0] = gx; d[1] = gy; d[2] = gz;
    }
    for (int c = tid; c < N_HEAD * CDIM; c += 128) {
        int h = c / CDIM, cc = c % CDIM;
        g_vcat[((size_t)h * N_RES + i) * 40 + cc] = prow[384 + c];
    }
}

// ---------------- tiled attention: block per (h, 32-row i-tile) ----------------
__global__ void attn_fused(const float* __restrict__ hw) {
    const float WL  = 0.5773502691896258f;
    const float WC2 = 0.11785113019775793f;
    int h = blockIdx.y;
    int i0 = blockIdx.x * 32;
    int tid = threadIdx.x;   // 256
    __shared__ float ks [CDIM][N_RES];
    __shared__ float tks[12][N_RES];
    __shared__ float qs [32][CDIM];
    __shared__ float tqs[32][12];
    for (int t = tid; t < N_RES * 4; t += 256) {
        int j = t >> 2, cq = (t & 3) * 4;
        float4 kv = *(const float4*)&g_proj[(size_t)j * NP + 192 + h * CDIM + cq];
        ks[cq + 0][j] = kv.x; ks[cq + 1][j] = kv.y;
        ks[cq + 2][j] = kv.z; ks[cq + 3][j] = kv.w;
    }
    for (int t = tid; t < 12 * N_RES; t += 256) tks[t / N_RES][t % N_RES] = g_tk[h * 12 * N_RES + t];
    for (int t = tid; t < 32 * CDIM; t += 256) {
        int il = t / CDIM, c = t % CDIM;
        qs[il][c] = g_proj[(size_t)(i0 + il) * NP + h * CDIM + c] * 0.25f;
    }
    for (int t = tid; t < 32 * 12; t += 256) {
        int il = t / 12, pd = t % 12;
        tqs[il][pd] = g_tq[(h * 12 + pd) * N_RES + i0 + il];
    }
    __syncthreads();
    float gam = log1pf(__expf(hw[h]));
    float coef = gam * WC2;
    int w = tid >> 5, lane = tid & 31;
    #pragma unroll
    for (int rr = 0; rr < 4; rr++) {
        int il = w * 4 + rr;
        int i = i0 + il;
        const float* brow = &g_bias[((size_t)h * N_RES + i) * N_RES];
        float lreg[12];
        float lmax = -1e30f;
        #pragma unroll
        for (int jj = 0; jj < 12; jj++) {
            int j = lane + jj * 32;
            float qk = 0.f;
            #pragma unroll
            for (int c = 0; c < CDIM; c++) qk += qs[il][c] * ks[c][j];
            float dist = 0.f;
            #pragma unroll
            for (int pd = 0; pd < 12; pd++) {
                float dlt = tqs[il][pd] - tks[pd][j];
                dist += dlt * dlt;
            }
            float lg = WL * (qk + brow[j] - coef * dist);
            lreg[jj] = lg;
            lmax = fmaxf(lmax, lg);
        }
        #pragma unroll
        for (int off = 16; off > 0; off >>= 1)
            lmax = fmaxf(lmax, __shfl_xor_sync(0xffffffffu, lmax, off));
        float s = 0.f;
        #pragma unroll
        for (int jj = 0; jj < 12; jj++) {
            float e = __expf(lreg[jj] - lmax);
            lreg[jj] = e;
            s += e;
        }
        #pragma unroll
        for (int off = 16; off > 0; off >>= 1)
            s += __shfl_xor_sync(0xffffffffu, s, off);
        float inv = 1.f / s;
        float* arow = &g_att[((size_t)h * N_RES + i) * N_RES];
        #pragma unroll
        for (int jj = 0; jj < 12; jj++)
            arow[lane + jj * 32] = lreg[jj] * inv;
    }
}

// ---------------- pairwise: block per (i, c-half) ----------------
__global__ void pairwise_kernel(const float* __restrict__ z) {
    int i = blockIdx.x;
    int ch = blockIdx.y;     // 0/1: c-columns [0,64) or [64,128)
    int tid = threadIdx.x;   // 256
    __shared__ float att_s[N_HEAD][N_RES];     // 18 KB
    __shared__ float4 part[8][N_HEAD][16];     // 24 KB
    for (int idx = tid; idx < N_HEAD * N_RES; idx += 256) {
        int h = idx / N_RES, j = idx % N_RES;
        att_s[h][j] = g_att[((size_t)h * N_RES + i) * N_RES + j];
    }
    __syncthreads();
    int c4 = tid & 15;       // float4 column within half
    int jr = tid >> 4;       // 16 j-slices
    const float4* zp = (const float4*)(z + (size_t)i * N_RES * C_Z) + ch * 16 + c4;
    float acc[N_HEAD][4];
    #pragma unroll
    for (int h = 0; h < N_HEAD; h++) {
        acc[h][0] = 0.f; acc[h][1] = 0.f; acc[h][2] = 0.f; acc[h][3] = 0.f;
    }
    for (int j = jr; j < N_RES; j += 16) {
        float4 zv = zp[j * 32];
        #pragma unroll
        for (int h = 0; h < N_HEAD; h++) {
            float a = att_s[h][j];
            acc[h][0] += a * zv.x; acc[h][1] += a * zv.y;
            acc[h][2] += a * zv.z; acc[h][3] += a * zv.w;
        }
    }
    // combine the two j-slices within each warp (lanes xor 16)
    #pragma unroll
    for (int h = 0; h < N_HEAD; h++) {
        #pragma unroll
        for (int q = 0; q < 4; q++)
            acc[h][q] += __shfl_xor_sync(0xffffffffu, acc[h][q], 16);
    }
    int w = tid >> 5;
    if ((tid & 16) == 0) {
        #pragma unroll
        for (int h = 0; h < N_HEAD; h++)
            part[w][h][c4] = make_float4(acc[h][0], acc[h][1], acc[h][2], acc[h][3]);
    }
    __syncthreads();
    if (tid < N_HEAD * 16) {
        int h = tid >> 4, cc = tid & 15;
        float4 r = part[0][h][cc];
        #pragma unroll
        for (int w2 = 1; w2 < 8; w2++) {
            float4 q = part[w2][h][cc];
            r.x += q.x; r.y += q.y; r.z += q.z; r.w += q.w;
        }
        *(float4*)&g_cat[(size_t)i * 2112 + 576 + h * C_Z + ch * 64 + cc * 4] = r;
    }
}

// ---------------- eo = att[h] @ vcat[h], fused with inverse warp/norm/concat ----------------
__global__ void vatt_post(const float* __restrict__ T) {
    int h = blockIdx.y;
    int i0 = blockIdx.x * 32;
    __shared__ float at[32][33];
    __shared__ float vc[32][41];
    __shared__ float eo_s[32][41];
    int tid = threadIdx.x;   // 320
    int col = tid % 40, rgrp = tid / 40;
    float acc[4] = {0.f, 0.f, 0.f, 0.f};
    for (int j0 = 0; j0 < N_RES; j0 += 32) {
        for (int idx = tid; idx < 1024; idx += 320) {
            int r = idx / 32, c = idx % 32;
            at[r][c] = g_att[((size_t)h * N_RES + i0 + r) * N_RES + j0 + c];
        }
        for (int idx = tid; idx < 1280; idx += 320) {
            int r = idx / 40, c = idx % 40;
            vc[r][c] = g_vcat[((size_t)h * N_RES + j0 + r) * 40 + c];
        }
        __syncthreads();
        #pragma unroll 8
        for (int jj = 0; jj < 32; jj++) {
            float b = vc[jj][col];
            #pragma unroll
            for (int rr = 0; rr < 4; rr++) acc[rr] += at[rgrp + rr * 8][jj] * b;
        }
        __syncthreads();
    }
    #pragma unroll
    for (int rr = 0; rr < 4; rr++)
        eo_s[rgrp + rr * 8][col] = acc[rr];
    __syncthreads();
    if (tid < 32) {
        int i = i0 + tid;
        const float* e = eo_s[tid];
        float* catp = &g_cat[(size_t)i * 2112];
        #pragma unroll
        for (int c = 0; c < CDIM; c++) catp[h * CDIM + c] = e[c];
        float R[9], tv[3];
        #pragma unroll
        for (int d = 0; d < 9; d++) R[d] = T[i * 16 + (d / 3) * 4 + (d % 3)];
        #pragma unroll
        for (int d = 0; d < 3; d++) tv[d] = T[i * 16 + d * 4 + 3];
        #pragma unroll
        for (int k = 0; k < N_PV; k++) {
            float px = e[16 + k * 3 + 0] - tv[0];
            float py = e[16 + k * 3 + 1] - tv[1];
            float pz = e[16 + k * 3 + 2] - tv[2];
            float lx = R[0] * px + R[3] * py + R[6] * pz;
            float ly = R[1] * px + R[4] * py + R[7] * pz;
            float lz = R[2] * px + R[5] * py + R[8] * pz;
            catp[192 + 0 * 96 + h * N_PV + k] = lx;
            catp[192 + 1 * 96 + h * N_PV + k] = ly;
            catp[192 + 2 * 96 + h * N_PV + k] = lz;
            catp[480 + h * N_PV + k] = sqrtf(lx * lx + ly * ly + lz * lz);
        }
    }
}

extern "C" void kernel_launch(void* const* d_in, const int* in_sizes, int n_in,
                              void* d_out, int out_size) {
    const float* s   = (const float*)d_in[0];
    const float* z   = (const float*)d_in[1];
    const float* T   = (const float*)d_in[2];
    const float* Wq  = (const float*)d_in[3];
    const float* bq  = (const float*)d_in[4];
    const float* Wk  = (const float*)d_in[5];
    const float* bk  = (const float*)d_in[6];
    const float* Wv  = (const float*)d_in[7];
    const float* bv  = (const float*)d_in[8];
    const float* Wqp = (const float*)d_in[9];
    const float* bqp = (const float*)d_in[10];
    const float* Wkp = (const float*)d_in[11];
    const float* bkp = (const float*)d_in[12];
    const float* Wvp = (const float*)d_in[13];
    const float* bvp = (const float*)d_in[14];
    const float* Wb  = (const float*)d_in[15];
    const float* bb  = (const float*)d_in[16];
    const float* Wo  = (const float*)d_in[17];
    const float* bo  = (const float*)d_in[18];
    const float* hw  = (const float*)d_in[19];
    float* out = (float*)d_out;

    float *p_proj, *p_Wcat, *p_bcat, *p_cat, *p_part;
    cudaGetSymbolAddress((void**)&p_proj, g_proj);
    cudaGetSymbolAddress((void**)&p_Wcat, g_Wcat);
    cudaGetSymbolAddress((void**)&p_bcat, g_bcat);
    cudaGetSymbolAddress((void**)&p_cat,  g_cat);
    cudaGetSymbolAddress((void**)&p_part, g_part);

    // 0) concat weights + Wb tf32 split
    prep_w<<<(C_S * NP + NP + C_Z * 16 + 255) / 256, 256>>>(Wq, Wk, Wv, Wqp, Wkp, Wvp,
                                                            bq, bk, bv, bqp, bkp, bvp, Wb);
    // 1) all six projections in one tf32 GEMM: s(384x384) @ Wcat(384x1152)
    gemm_tf32<<<dim3(NP / 64, N_RES / 128, 1), 256>>>(s, C_S, p_Wcat, NP, p_bcat, p_proj, NP, C_S);
    // 2) bias from z via tensor cores (75 MB stream)
    bias_mma<<<NROWS / 128, 256>>>(z, bb);
    // 3) frame transforms
    transform_kernel<<<N_RES, 128>>>(T);
    // 4) tiled attention + softmax
    attn_fused<<<dim3(N_RES / 32, N_HEAD), 256>>>(hw);
    // 5) pairwise (writes cat[576:2112)) — second 75 MB z stream, c-split x2
    pairwise_kernel<<<dim3(N_RES, 2), 256>>>(z);
    // 6) att @ [v|vt] + fused inverse warp/norm/concat (writes cat[0:576))
    vatt_post<<<dim3(12, 12), 320>>>(T);
    // 7) final projection: cat(384x2112) @ Wo(2112x384), tf32 split-K=6
    gemm_tf32<<<dim3(C_S / 64, N_RES / 128, KSPLIT), 256>>>(p_cat, 2112, Wo, C_S, nullptr, p_part, C_S, 2112 / KSPLIT);
    reduce_out<<<(N_RES * C_S / 4 + 255) / 256, 256>>>(bo, out);
}